// round 7
// baseline (speedup 1.0000x reference)
#include <cuda_runtime.h>
#include <cuda_bf16.h>
#include <stdint.h>

// Problem constants
#define NR 4096
#define DIM 1024                 // bytes/row in fp8
#define NT 32                    // 128-row tiles per dim
#define NBLK 528                 // upper-tri 128x128 tiles
#define BKB 64                   // K bytes per stage
#define NSTG 16                  // 1024 / 64
#define STAGE_BYTES 16384        // A 128x64B + B 128x64B
#define SMEM_TOTAL (4 * STAGE_BYTES)   // 64KB, 4-stage ring -> 2 CTAs/SM

// Scratch (static device globals; no runtime allocation)
__device__ uint8_t g_zq[NR * DIM];   // normalized z1 * 16, e4m3 (4 MB, L2-resident)
__device__ float g_sq[NR];
__device__ float g_pos[NR];
__device__ float g_negpart[NBLK];
__device__ unsigned g_ticket;        // last-CTA-done ticket (reset each run)

__device__ __forceinline__ uint32_t su32(const void* p) {
    return (uint32_t)__cvta_generic_to_shared(p);
}
__device__ __forceinline__ void cpasync16(uint32_t dst, const void* g) {
    asm volatile("cp.async.cg.shared.global [%0], [%1], 16;" :: "r"(dst), "l"(g));
}
#define CP_COMMIT() asm volatile("cp.async.commit_group;")
#define CP_WAIT(n)  asm volatile("cp.async.wait_group %0;" :: "n"(n))

#define LDMX4(R, addr) \
    asm volatile("ldmatrix.sync.aligned.m8n8.x4.shared.b16 {%0,%1,%2,%3}, [%4];" \
                 : "=r"((R)[0]), "=r"((R)[1]), "=r"((R)[2]), "=r"((R)[3]) : "r"(addr))

__device__ __forceinline__ void mma16832(float* c, const uint32_t* a, const uint32_t* b) {
    asm volatile(
        "mma.sync.aligned.m16n8k32.row.col.f32.e4m3.e4m3.f32 "
        "{%0,%1,%2,%3}, {%4,%5,%6,%7}, {%8,%9}, {%0,%1,%2,%3};"
        : "+f"(c[0]), "+f"(c[1]), "+f"(c[2]), "+f"(c[3])
        : "r"(a[0]), "r"(a[1]), "r"(a[2]), "r"(a[3]), "r"(b[0]), "r"(b[1]));
}

__device__ __forceinline__ uint32_t pack4_e4m3(float v0, float v1, float v2, float v3) {
    uint16_t h01, h23;
    asm("cvt.rn.satfinite.e4m3x2.f32 %0, %1, %2;" : "=h"(h01) : "f"(v1), "f"(v0));
    asm("cvt.rn.satfinite.e4m3x2.f32 %0, %1, %2;" : "=h"(h23) : "f"(v3), "f"(v2));
    return (uint32_t)h01 | ((uint32_t)h23 << 16);
}

// SW64 swizzle for 64B-wide rows (conflict-free ldmatrix over 8 rows)
__device__ __forceinline__ uint32_t sw64(uint32_t off) {
    return off ^ ((off >> 3) & 0x30);
}

// -------------------------------------------------------------------------
// Kernel 1: warp-per-row-pair normalize (best measured variant: R5).
// 1024 blocks x 128 thr. Emits e4m3 (z * 16).
// -------------------------------------------------------------------------
__global__ __launch_bounds__(128) void normalize_kernel(const float* __restrict__ z) {
    int warp = threadIdx.x >> 5, lane = threadIdx.x & 31;
    int row = blockIdx.x * 4 + warp;

    const float4* z1p = (const float4*)(z + (size_t)row * DIM);
    const float4* z2p = (const float4*)(z + (size_t)(row + NR) * DIM);

    float4 a[8];
    float s1 = 0.f, s2 = 0.f, s12 = 0.f;
    #pragma unroll
    for (int i = 0; i < 8; i++) {
        a[i] = z1p[lane + 32 * i];
        float4 b = z2p[lane + 32 * i];
        s1  += a[i].x * a[i].x + a[i].y * a[i].y + a[i].z * a[i].z + a[i].w * a[i].w;
        s2  += b.x * b.x + b.y * b.y + b.z * b.z + b.w * b.w;
        s12 += a[i].x * b.x + a[i].y * b.y + a[i].z * b.z + a[i].w * b.w;
    }
    #pragma unroll
    for (int o = 16; o; o >>= 1) {
        s1  += __shfl_xor_sync(0xFFFFFFFFu, s1, o);
        s2  += __shfl_xor_sync(0xFFFFFFFFu, s2, o);
        s12 += __shfl_xor_sync(0xFFFFFFFFu, s12, o);
    }
    float inv1 = 1.f / fmaxf(sqrtf(s1), 1e-12f);
    float inv2 = 1.f / fmaxf(sqrtf(s2), 1e-12f);
    float q1 = 16.f * inv1;

    uint32_t* dst = (uint32_t*)(g_zq + (size_t)row * DIM);
    #pragma unroll
    for (int i = 0; i < 8; i++) {
        dst[lane + 32 * i] = pack4_e4m3(a[i].x * q1, a[i].y * q1, a[i].z * q1, a[i].w * q1);
    }
    if (lane == 0) {
        float n1sq = s1 * inv1 * inv1;
        float n2sq = s2 * inv2 * inv2;
        float dp = n1sq + n2sq - 2.f * s12 * inv1 * inv2;
        g_pos[row] = logf(__expf(-0.5f * dp) + 1e-8f) + 1.f;
        g_sq[row] = n1sq;
    }
}

// -------------------------------------------------------------------------
// Kernel 2: fp8 Gram + fused exp-reduce + fused last-CTA finalize.
// 528 CTAs x 256 thr, 2 CTAs/SM. CTA tile 128x128; warp tile 64x32.
// 16 K-stages of 64B, 4-stage ring with ONE barrier per stage.
// -------------------------------------------------------------------------
__global__ __launch_bounds__(256, 2) void gram_kernel(float* __restrict__ out) {
    extern __shared__ uint8_t dsm[];
    uint32_t smem_base = su32(dsm);
    int tid = threadIdx.x;
    int warp = tid >> 5, lane = tid & 31;
    int wr = warp >> 2, wc = warp & 3;   // warp grid 2 x 4 (rows x cols)

    // bid -> (ti, tj), tj >= ti
    int ti = 0, rem = blockIdx.x;
    #pragma unroll 1
    while (rem >= NT - ti) { rem -= NT - ti; ti++; }
    int tj = ti + rem;

    // diagonal tiles: warps whose whole 64x32 patch is strictly below the
    // diagonal produce nothing -> skip LDSM+MMA (still do loads/barriers).
    bool active = !(ti == tj && (wc * 32 + 32 <= wr * 64));

    const uint8_t* Abase = g_zq + (size_t)ti * 128 * DIM;
    const uint8_t* Bbase = g_zq + (size_t)tj * 128 * DIM;

    float acc[4][4][4];
    #pragma unroll
    for (int i = 0; i < 4; i++)
        #pragma unroll
        for (int j = 0; j < 4; j++)
            #pragma unroll
            for (int e = 0; e < 4; e++) acc[i][j][e] = 0.f;

    #define LOAD_STAGE(s, slot)                                                   \
        do {                                                                      \
            uint32_t base_ = smem_base + (slot) * STAGE_BYTES;                    \
            const uint8_t* Ak = Abase + (s) * BKB;                                \
            const uint8_t* Bk = Bbase + (s) * BKB;                                \
            _Pragma("unroll")                                                     \
            for (int x = tid; x < 512; x += 256) {                                \
                int r_ = x >> 2, c_ = x & 3;                                      \
                uint32_t off = sw64((uint32_t)(r_ * 64 + c_ * 16));               \
                cpasync16(base_ + off, Ak + (size_t)r_ * DIM + c_ * 16);          \
            }                                                                     \
            _Pragma("unroll")                                                     \
            for (int x = tid; x < 512; x += 256) {                                \
                int r_ = x >> 2, c_ = x & 3;                                      \
                uint32_t off = sw64((uint32_t)(r_ * 64 + c_ * 16));               \
                cpasync16(base_ + 8192 + off, Bk + (size_t)r_ * DIM + c_ * 16);   \
            }                                                                     \
            CP_COMMIT();                                                          \
        } while (0)

    LOAD_STAGE(0, 0);
    LOAD_STAGE(1, 1);
    LOAD_STAGE(2, 2);

    #pragma unroll 1
    for (int s = 0; s < NSTG; s++) {
        // ensure stage s landed; one barrier also fences last stage's readers
        if (s <= NSTG - 3)      CP_WAIT(2);
        else if (s == NSTG - 2) CP_WAIT(1);
        else                    CP_WAIT(0);
        __syncthreads();

        if (s + 3 < NSTG) LOAD_STAGE(s + 3, (s + 3) & 3);

        if (active) {
            uint32_t sa = smem_base + (s & 3) * STAGE_BYTES;
            uint32_t sb = sa + 8192;
            #pragma unroll
            for (int kk = 0; kk < 2; kk++) {
                uint32_t af[4][4];
                #pragma unroll
                for (int mi = 0; mi < 4; mi++) {
                    int r = wr * 64 + mi * 16 + (lane & 7) + ((lane >> 3) & 1) * 8;
                    int cb = kk * 32 + ((lane >> 4) & 1) * 16;
                    LDMX4(af[mi], sa + sw64((uint32_t)(r * 64 + cb)));
                }
                uint32_t bf[4][2];
                #pragma unroll
                for (int p = 0; p < 2; p++) {
                    int r = wc * 32 + p * 16 + ((lane >> 4) & 1) * 8 + (lane & 7);
                    int cb = kk * 32 + ((lane >> 3) & 1) * 16;
                    uint32_t t[4];
                    LDMX4(t, sb + sw64((uint32_t)(r * 64 + cb)));
                    bf[2 * p + 0][0] = t[0]; bf[2 * p + 0][1] = t[1];
                    bf[2 * p + 1][0] = t[2]; bf[2 * p + 1][1] = t[3];
                }
                #pragma unroll
                for (int mi = 0; mi < 4; mi++)
                    #pragma unroll
                    for (int ni = 0; ni < 4; ni++)
                        mma16832(acc[mi][ni], af[mi], bf[ni]);
            }
        }
    }
    __syncthreads();   // buffers dead; reuse smem for sq staging

    float* sqi_sh = (float*)dsm;          // 128 floats
    float* sqj_sh = (float*)dsm + 128;    // 128 floats
    if (tid < 128) sqi_sh[tid] = g_sq[ti * 128 + tid];
    else           sqj_sh[tid - 128] = g_sq[tj * 128 + (tid - 128)];
    __syncthreads();

    // epilogue: acc = 256 * dot; d2 = si + sj - acc/128.
    float local = 0.f;
    if (active) {
        int r0 = lane >> 2, c0 = (lane & 3) * 2;
        #pragma unroll
        for (int mi = 0; mi < 4; mi++) {
            float si0 = sqi_sh[wr * 64 + mi * 16 + r0];
            float si1 = sqi_sh[wr * 64 + mi * 16 + r0 + 8];
            int gi0 = ti * 128 + wr * 64 + mi * 16 + r0;
            #pragma unroll
            for (int ni = 0; ni < 4; ni++) {
                int jl = wc * 32 + ni * 8 + c0;
                float sj0 = sqj_sh[jl], sj1 = sqj_sh[jl + 1];
                int gj0 = tj * 128 + jl;
                #pragma unroll
                for (int e = 0; e < 4; e++) {
                    float si = (e >> 1) ? si1 : si0;
                    float sj = (e & 1) ? sj1 : sj0;
                    int gi = gi0 + ((e >> 1) ? 8 : 0);
                    int gj = gj0 + (e & 1);
                    float d2 = fmaxf(si + sj - acc[mi][ni][e] * (1.f / 128.f), 0.f);
                    if (gj > gi) local += 2.f * __expf(-0.5f * d2);
                }
            }
        }
    }

    #pragma unroll
    for (int o = 16; o; o >>= 1) local += __shfl_xor_sync(0xFFFFFFFFu, local, o);
    __shared__ float part[8];
    __shared__ unsigned s_last;
    if (lane == 0) part[warp] = local;
    __syncthreads();
    if (tid == 0) {
        float tot = 0.f;
        #pragma unroll
        for (int i = 0; i < 8; i++) tot += part[i];
        g_negpart[blockIdx.x] = tot;
        __threadfence();
        unsigned t = atomicAdd(&g_ticket, 1u);
        s_last = (t == NBLK - 1) ? 1u : 0u;
    }
    __syncthreads();

    // last CTA performs the deterministic finalize (replay-safe: resets ticket)
    if (s_last) {
        __threadfence();   // acquire all g_negpart / g_pos writes
        double* sh = (double*)dsm;
        double p = 0.0;
        for (int i = tid; i < NR; i += 256) p += (double)g_pos[i];
        sh[tid] = p;
        __syncthreads();
        for (int s = 128; s; s >>= 1) {
            if (tid < s) sh[tid] += sh[tid + s];
            __syncthreads();
        }
        double pos_sum = sh[0];
        __syncthreads();

        double n = 0.0;
        for (int i = tid; i < NBLK; i += 256) n += (double)g_negpart[i];
        sh[tid] = n;
        __syncthreads();
        for (int s = 128; s; s >>= 1) {
            if (tid < s) sh[tid] += sh[tid + s];
            __syncthreads();
        }
        if (tid == 0) {
            double star_mean = sh[0] / ((double)NR * (double)(NR - 1)) + 1e-8;
            out[0] = (float)(-(pos_sum / (double)NR) + 64.0 * star_mean);
            g_ticket = 0;   // reset for next graph replay
            __threadfence();
        }
    }
}

extern "C" void kernel_launch(void* const* d_in, const int* in_sizes, int n_in,
                              void* d_out, int out_size) {
    const float* z = (const float*)d_in[0];
    float* out = (float*)d_out;
    cudaFuncSetAttribute(gram_kernel, cudaFuncAttributeMaxDynamicSharedMemorySize,
                         SMEM_TOTAL);
    normalize_kernel<<<1024, 128>>>(z);
    gram_kernel<<<NBLK, 256, SMEM_TOTAL>>>(out);
}